// round 6
// baseline (speedup 1.0000x reference)
#include <cuda_runtime.h>
#include <cstdint>

#define B_SZ 256
#define C_SZ 3
#define H_SZ 224
#define W_SZ 224
#define P_SZ 1024
#define E_SZ 384

// Block: (96, 4). threadIdx.x indexes groups of 4 consecutive e (96*4 = 384).
// threadIdx.y indexes p within a 4-wide sub-tile; each block handles 32 p's
// for one batch b. Gathers are batched up-front for MLP.
__global__ __launch_bounds__(384) void patch_embed_kernel(
    const float* __restrict__ x,      // (B, C, H, W)
    const int*   __restrict__ curve,  // (P, 2): [:,0]=x-coord, [:,1]=y-coord
    const float* __restrict__ Wm,     // (E, C) row-major
    const float* __restrict__ bias,   // (E,)
    float* __restrict__ out)          // (B, 1, P, E)
{
    __shared__ float sW[E_SZ * C_SZ];
    __shared__ float sB[E_SZ];

    const int tid = threadIdx.y * 96 + threadIdx.x;   // 0..383
    sW[tid]        = __ldg(&Wm[tid]);
    sW[tid + 384]  = __ldg(&Wm[tid + 384]);
    sW[tid + 768]  = __ldg(&Wm[tid + 768]);
    sB[tid]        = __ldg(&bias[tid]);
    __syncthreads();

    const int e0 = threadIdx.x * 4;
    float4 w0, w1, w2, bb;
    w0.x = sW[(e0+0)*3+0]; w0.y = sW[(e0+1)*3+0]; w0.z = sW[(e0+2)*3+0]; w0.w = sW[(e0+3)*3+0];
    w1.x = sW[(e0+0)*3+1]; w1.y = sW[(e0+1)*3+1]; w1.z = sW[(e0+2)*3+1]; w1.w = sW[(e0+3)*3+1];
    w2.x = sW[(e0+0)*3+2]; w2.y = sW[(e0+1)*3+2]; w2.z = sW[(e0+2)*3+2]; w2.w = sW[(e0+3)*3+2];
    bb.x = sB[e0+0]; bb.y = sB[e0+1]; bb.z = sB[e0+2]; bb.w = sB[e0+3];

    const int b = blockIdx.y;
    const float* xb = x + (size_t)b * (C_SZ * H_SZ * W_SZ);
    float* outb = out + (size_t)b * (P_SZ * E_SZ);

    const int pbase = blockIdx.x * 32 + threadIdx.y;
    const int2* __restrict__ cv2 = (const int2*)curve;

    // Phase 1: batch all index loads + gathers (MLP ~24 outstanding loads).
    float g0[8], g1[8], g2[8];
    #pragma unroll
    for (int i = 0; i < 8; i++) {
        const int2 cv = __ldg(&cv2[pbase + i * 4]);
        const int off = cv.y * W_SZ + cv.x;
        g0[i] = __ldg(xb + off);
        g1[i] = __ldg(xb + H_SZ * W_SZ + off);
        g2[i] = __ldg(xb + 2 * H_SZ * W_SZ + off);
    }

    // Phase 2: FMA + streaming stores (write-once output, bypass L2 persist).
    #pragma unroll
    for (int i = 0; i < 8; i++) {
        const int p = pbase + i * 4;
        float4 r;
        r.x = fmaf(g0[i], w0.x, fmaf(g1[i], w1.x, fmaf(g2[i], w2.x, bb.x)));
        r.y = fmaf(g0[i], w0.y, fmaf(g1[i], w1.y, fmaf(g2[i], w2.y, bb.y)));
        r.z = fmaf(g0[i], w0.z, fmaf(g1[i], w1.z, fmaf(g2[i], w2.z, bb.z)));
        r.w = fmaf(g0[i], w0.w, fmaf(g1[i], w1.w, fmaf(g2[i], w2.w, bb.w)));
        float4* dst = (float4*)(outb + (size_t)p * E_SZ) + threadIdx.x;
        __stcs(dst, r);
    }
}

extern "C" void kernel_launch(void* const* d_in, const int* in_sizes, int n_in,
                              void* d_out, int out_size) {
    const float* x     = (const float*)d_in[0];
    const int*   curve = (const int*)d_in[1];
    const float* Wm    = (const float*)d_in[2];
    const float* bias  = (const float*)d_in[3];
    float* out = (float*)d_out;

    dim3 block(96, 4);
    dim3 grid(P_SZ / 32, B_SZ);
    patch_embed_kernel<<<grid, block>>>(x, curve, Wm, bias, out);
}